// round 8
// baseline (speedup 1.0000x reference)
#include <cuda_runtime.h>
#include <math.h>

#define BATCH 2048
#define XF    1024
#define XF4   (XF / 4)
#define G     16

#define NBLK  256
#define TPB   256
#define CH    32                // row chunks (64 rows each)
#define RPCH  (BATCH / CH)      // 64
#define RPT   8                 // rows per thread per phase

// Scratch (allocation-free: __device__ globals)
__device__ float g_p0[CH * XF];
__device__ float g_p1[CH * XF];
__device__ float g_p2[CH * XF];
__device__ float g_mean[XF];

__device__ unsigned g_count = 0;
__device__ unsigned g_gen   = 0;   // monotone generation (replay-safe: only
                                   // compared against value read at entry)

__device__ __forceinline__ void grid_barrier() {
    __syncthreads();
    if (threadIdx.x == 0) {
        volatile unsigned* genp = (volatile unsigned*)&g_gen;
        unsigned gen = *genp;
        __threadfence();                       // publish this block's stores
        if (atomicAdd(&g_count, 1u) == NBLK - 1u) {
            g_count = 0;                       // safe: no one adds until gen bumps
            __threadfence();
            *genp = gen + 1u;                  // release
        } else {
            while (*genp == gen) { }           // plain volatile load spin
        }
        __threadfence();                       // acquire
    }
    __syncthreads();
}

__global__ __launch_bounds__(TPB, 2)
void fused(const float* __restrict__ xf,
           const float* __restrict__ wp,
           float* __restrict__ out) {
    __shared__ float4 sh[8][32];
    __shared__ float4 shm[32];
    __shared__ float  f1[4][64], f2[4][64];
    __shared__ float  s_m[64], s_a[64], s_b[64];

    const int tid = threadIdx.x;
    const int b   = blockIdx.x;

    // ================= Phase 1: per-chunk column sums =================
    {
        int cg = b & 7, chunk = b >> 3;            // 8 col-groups x 32 chunks
        int c4 = tid & 31, rg = tid >> 5;
        int col4 = cg * 32 + c4;
        int row0 = chunk * RPCH + rg * RPT;

        const float4* p = (const float4*)xf + (size_t)row0 * XF4 + col4;
        float4 s = make_float4(0.f, 0.f, 0.f, 0.f);
#pragma unroll
        for (int r = 0; r < RPT; r++) {
            float4 x = p[(size_t)r * XF4];
            s.x += x.x; s.y += x.y; s.z += x.z; s.w += x.w;
        }
        sh[rg][c4] = s;
        __syncthreads();
        if (rg == 0) {
            float4 t = sh[0][c4];
#pragma unroll
            for (int i = 1; i < 8; i++) {
                float4 u = sh[i][c4];
                t.x += u.x; t.y += u.y; t.z += u.z; t.w += u.w;
            }
            ((float4*)(g_p0 + chunk * XF))[col4] = t;
        }
    }
    grid_barrier();

    // ======= Phase 2: fold mean partials (in-block), stats partials =======
    {
        int cg = b & 7, chunk = b >> 3;
        int c4 = tid & 31, rg = tid >> 5;
        int col4 = cg * 32 + c4;
        int row0 = chunk * RPCH + rg * RPT;

        float4 s = make_float4(0.f, 0.f, 0.f, 0.f);
#pragma unroll
        for (int i = 0; i < 4; i++) {
            float4 u = ((const float4*)(g_p0 + (rg * 4 + i) * XF))[col4];
            s.x += u.x; s.y += u.y; s.z += u.z; s.w += u.w;
        }
        sh[rg][c4] = s;
        __syncthreads();
        if (rg == 0) {
            float4 t = sh[0][c4];
#pragma unroll
            for (int i = 1; i < 8; i++) {
                float4 u = sh[i][c4];
                t.x += u.x; t.y += u.y; t.z += u.z; t.w += u.w;
            }
            const float inv = 1.0f / BATCH;
            t.x *= inv; t.y *= inv; t.z *= inv; t.w *= inv;
            shm[c4] = t;
            if (chunk == 0) ((float4*)g_mean)[col4] = t;
        }
        __syncthreads();
        float4 m = shm[c4];

        const float4* p = (const float4*)xf + (size_t)row0 * XF4 + col4;
        float4 s1 = make_float4(0.f, 0.f, 0.f, 0.f);
        float4 s2 = make_float4(0.f, 0.f, 0.f, 0.f);
#pragma unroll
        for (int r = 0; r < RPT; r++) {
            float4 x = p[(size_t)r * XF4];
            float vx = fmaxf(x.x - m.x, 0.f);
            float vy = fmaxf(x.y - m.y, 0.f);
            float vz = fmaxf(x.z - m.z, 0.f);
            float vw = fmaxf(x.w - m.w, 0.f);
            s1.x += vx; s1.y += vy; s1.z += vz; s1.w += vw;
            s2.x += vx * vx; s2.y += vy * vy; s2.z += vz * vz; s2.w += vw * vw;
        }
        __syncthreads();
        sh[rg][c4] = s1;
        __syncthreads();
        if (rg == 0) {
            float4 t = sh[0][c4];
#pragma unroll
            for (int i = 1; i < 8; i++) {
                float4 u = sh[i][c4];
                t.x += u.x; t.y += u.y; t.z += u.z; t.w += u.w;
            }
            ((float4*)(g_p1 + chunk * XF))[col4] = t;
        }
        __syncthreads();
        sh[rg][c4] = s2;
        __syncthreads();
        if (rg == 0) {
            float4 t = sh[0][c4];
#pragma unroll
            for (int i = 1; i < 8; i++) {
                float4 u = sh[i][c4];
                t.x += u.x; t.y += u.y; t.z += u.z; t.w += u.w;
            }
            ((float4*)(g_p2 + chunk * XF))[col4] = t;
        }
    }
    grid_barrier();

    // ========== Phase 3: fold a,b for this 64-col tile; output ==========
    {
        int tx = b & 15, ty = b >> 4;              // 16 col-tiles x 16 row-tiles
        int col0 = tx * 64;

        {
            int cc = tid & 63, gg = tid >> 6;
            int col = col0 + cc;
            float s1 = 0.f, s2 = 0.f;
#pragma unroll
            for (int i = 0; i < 8; i++) {
                int idx = (gg * 8 + i) * XF + col;
                s1 += g_p1[idx];
                s2 += g_p2[idx];
            }
            f1[gg][cc] = s1;
            f2[gg][cc] = s2;
        }
        __syncthreads();
        if (tid < 64) {
            float s1 = f1[0][tid] + f1[1][tid] + f1[2][tid] + f1[3][tid];
            float s2 = f2[0][tid] + f2[1][tid] + f2[2][tid] + f2[3][tid];
            float mu  = s1 * (1.0f / BATCH);
            float var = (s2 - (float)BATCH * mu * mu) * (1.0f / (BATCH - 1));
            float a   = wp[0] * rsqrtf(var);
            s_m[tid] = g_mean[col0 + tid];
            s_a[tid] = a;
            s_b[tid] = -a * mu;
        }
        __syncthreads();

        int cidx = tid & 15;
        int ridx = tid >> 4;
        int col  = col0 + cidx * 4;

        float4 m = *(const float4*)(s_m + cidx * 4);
        float4 a = *(const float4*)(s_a + cidx * 4);
        float4 bb = *(const float4*)(s_b + cidx * 4);

#pragma unroll
        for (int j = 0; j < 8; j++) {              // 8 rows per thread
            int row = ty * 128 + ridx + j * 16;
            float4 x = *(const float4*)(xf + (size_t)row * XF + col);
            float4 v;
            v.x = fmaxf(x.x - m.x, 0.f) * a.x + bb.x;
            v.y = fmaxf(x.y - m.y, 0.f) * a.y + bb.y;
            v.z = fmaxf(x.z - m.z, 0.f) * a.z + bb.z;
            v.w = fmaxf(x.w - m.w, 0.f) * a.w + bb.w;

            float* orow = out + (size_t)row * (G * XF) + col;
#pragma unroll
            for (int k = 0; k < G; k++)
                __stcs((float4*)(orow + (size_t)k * XF), v);
        }
    }
}

extern "C" void kernel_launch(void* const* d_in, const int* in_sizes, int n_in,
                              void* d_out, int out_size) {
    const float* xf = (const float*)d_in[0];
    const float* wp = (const float*)d_in[1];
    float* out = (float*)d_out;
    fused<<<NBLK, TPB>>>(xf, wp, out);
}